// round 1
// baseline (speedup 1.0000x reference)
#include <cuda_runtime.h>
#include <cstddef>

// Problem constants (fixed by the dataset)
#define NN   50000
#define EE   800000
#define GG   512
#define CH   128
#define CIN  64
#define NEG_SLOPE 0.01f

// ---------------------------------------------------------------------------
// Device-global scratch (no allocation allowed in kernel_launch)
// ---------------------------------------------------------------------------
__device__ float g_hA[NN * CH];
__device__ float g_hB[NN * CH];
__device__ float g_agg[NN * CH];
__device__ float g_inv[NN];
__device__ int   g_deg[NN];
__device__ int   g_rowptr[NN + 1];
__device__ int   g_cursor[NN];
__device__ int   g_col[EE];
__device__ float g_pool[GG * CH];
__device__ float g_gcnt[GG];

// ---------------------------------------------------------------------------
// Utility kernels
// ---------------------------------------------------------------------------
__global__ void k_zero_f(float* p, int n) {
    int i = blockIdx.x * blockDim.x + threadIdx.x;
    if (i < n) p[i] = 0.0f;
}
__global__ void k_zero_i(int* p, int n) {
    int i = blockIdx.x * blockDim.x + threadIdx.x;
    if (i < n) p[i] = 0;
}

// Count in-degree per destination node
__global__ void k_count(const int* __restrict__ dst) {
    int i = blockIdx.x * blockDim.x + threadIdx.x;
    if (i < EE) atomicAdd(&g_deg[dst[i]], 1);
}

// Single-block exclusive scan over degrees -> rowptr, cursor, inv_deg
__global__ void k_scan() {
    __shared__ int sdata[1024];
    __shared__ int s_total;
    const int tid = threadIdx.x;
    if (tid == 0) s_total = 0;
    __syncthreads();
    for (int base = 0; base < NN; base += 1024) {
        int i = base + tid;
        int v = (i < NN) ? g_deg[i] : 0;
        sdata[tid] = v;
        __syncthreads();
        // Hillis-Steele inclusive scan
        #pragma unroll
        for (int off = 1; off < 1024; off <<= 1) {
            int t = (tid >= off) ? sdata[tid - off] : 0;
            __syncthreads();
            sdata[tid] += t;
            __syncthreads();
        }
        int incl = sdata[tid];
        int excl = incl - v;
        int run = s_total;
        if (i < NN) {
            g_rowptr[i] = run + excl;
            g_cursor[i] = run + excl;
            g_inv[i] = 1.0f / (float)max(v, 1);
        }
        __syncthreads();
        if (tid == 1023) s_total = run + incl;
        __syncthreads();
    }
    if (tid == 0) g_rowptr[NN] = s_total;
}

// Bucket edges into CSR (col = src sorted by dst)
__global__ void k_fill(const int* __restrict__ src, const int* __restrict__ dst) {
    int i = blockIdx.x * blockDim.x + threadIdx.x;
    if (i < EE) {
        int d = dst[i];
        int pos = atomicAdd(&g_cursor[d], 1);
        g_col[pos] = src[i];
    }
}

// ---------------------------------------------------------------------------
// Mean aggregation: one warp per destination node, gather-sum neighbor rows.
// Writes agg already divided by max(deg,1).
// ---------------------------------------------------------------------------
template <int C>
__global__ void k_agg(const float* __restrict__ h, float* __restrict__ agg) {
    int gw = (blockIdx.x * blockDim.x + threadIdx.x) >> 5;
    if (gw >= NN) return;
    int lane = threadIdx.x & 31;
    int b = g_rowptr[gw], e = g_rowptr[gw + 1];
    float iv = g_inv[gw];
    if constexpr (C == 128) {
        const float4* hp = (const float4*)h;
        float4 acc = make_float4(0.f, 0.f, 0.f, 0.f);
        for (int j = b; j < e; j++) {
            int s = g_col[j];
            float4 v = hp[s * 32 + lane];
            acc.x += v.x; acc.y += v.y; acc.z += v.z; acc.w += v.w;
        }
        float4 o;
        o.x = acc.x * iv; o.y = acc.y * iv; o.z = acc.z * iv; o.w = acc.w * iv;
        ((float4*)agg)[gw * 32 + lane] = o;
    } else {  // C == 64
        const float2* hp = (const float2*)h;
        float2 acc = make_float2(0.f, 0.f);
        for (int j = b; j < e; j++) {
            int s = g_col[j];
            float2 v = hp[s * 32 + lane];
            acc.x += v.x; acc.y += v.y;
        }
        float2 o; o.x = acc.x * iv; o.y = acc.y * iv;
        ((float2*)agg)[gw * 32 + lane] = o;
    }
}

// ---------------------------------------------------------------------------
// Fused SAGEConv GEMM:
//   Out[m][n] = agg[m][:] @ Wl + h[m][:] @ Wr + bias[n], then activation.
// Treated as one GEMM over concatenated K = 2*KH.
// BM=64, BN=128, BK=16, 256 threads, each thread 8x4 outputs.
// ACT: 0=none, 1=relu, 2=leaky(0.01)
// ---------------------------------------------------------------------------
template <int KH, int ACT>
__global__ __launch_bounds__(256) void k_gemm(
    const float* __restrict__ A,   // aggregated (pre-normalized), [NN][KH]
    const float* __restrict__ H,   // node features, [NN][KH]
    const float* __restrict__ Wl,  // [KH][128]
    const float* __restrict__ Wr,  // [KH][128]
    const float* __restrict__ bias,// [128]
    float* __restrict__ Out)       // [NN][128]
{
    constexpr int BM = 64, BN = 128, BK = 16, KT = 2 * KH;
    __shared__ __align__(16) float As[BK][BM];
    __shared__ __align__(16) float Ws[BK][BN];

    const int tid = threadIdx.x;
    const int row0 = blockIdx.x * BM;
    const int cx = tid & 31;        // column group (4 cols each)
    const int ry = tid >> 5;        // row group (8 rows each)
    const int lm = tid >> 2;        // A-load row (0..63)
    const int lk = (tid & 3) * 4;   // A-load k-offset (0,4,8,12)
    const int wn = (tid & 31) * 4;  // W-load column
    const int wk = tid >> 5;        // W-load k (0..7; +8 in second pass)

    float acc[8][4];
    #pragma unroll
    for (int r = 0; r < 8; r++)
        #pragma unroll
        for (int c = 0; c < 4; c++) acc[r][c] = 0.0f;

    for (int kt = 0; kt < KT; kt += BK) {
        // --- load A tile (64 x 16): float4 per thread, coalesced along k ---
        {
            int m = row0 + lm;
            int kg = kt + lk;
            float4 v = make_float4(0.f, 0.f, 0.f, 0.f);
            if (m < NN) {
                const float* p = (kg < KH) ? (A + (size_t)m * KH + kg)
                                           : (H + (size_t)m * KH + (kg - KH));
                v = *(const float4*)p;
            }
            As[lk + 0][lm] = v.x;
            As[lk + 1][lm] = v.y;
            As[lk + 2][lm] = v.z;
            As[lk + 3][lm] = v.w;
        }
        // --- load W tile (16 x 128): two float4 per thread, coalesced ---
        #pragma unroll
        for (int t = 0; t < 2; t++) {
            int kk = wk + t * 8;
            int kg = kt + kk;
            const float* p = (kg < KH) ? (Wl + (size_t)kg * BN + wn)
                                       : (Wr + (size_t)(kg - KH) * BN + wn);
            *(float4*)&Ws[kk][wn] = *(const float4*)p;
        }
        __syncthreads();

        #pragma unroll
        for (int kk = 0; kk < BK; kk++) {
            float4 w = *(const float4*)&Ws[kk][cx * 4];
            #pragma unroll
            for (int r = 0; r < 8; r++) {
                float a = As[kk][ry * 8 + r];
                acc[r][0] += a * w.x;
                acc[r][1] += a * w.y;
                acc[r][2] += a * w.z;
                acc[r][3] += a * w.w;
            }
        }
        __syncthreads();
    }

    float4 bb = *(const float4*)&bias[cx * 4];
    #pragma unroll
    for (int r = 0; r < 8; r++) {
        int m = row0 + ry * 8 + r;
        if (m < NN) {
            float4 v;
            v.x = acc[r][0] + bb.x;
            v.y = acc[r][1] + bb.y;
            v.z = acc[r][2] + bb.z;
            v.w = acc[r][3] + bb.w;
            if (ACT == 1) {
                v.x = fmaxf(v.x, 0.f); v.y = fmaxf(v.y, 0.f);
                v.z = fmaxf(v.z, 0.f); v.w = fmaxf(v.w, 0.f);
            } else if (ACT == 2) {
                v.x = (v.x > 0.f) ? v.x : NEG_SLOPE * v.x;
                v.y = (v.y > 0.f) ? v.y : NEG_SLOPE * v.y;
                v.z = (v.z > 0.f) ? v.z : NEG_SLOPE * v.z;
                v.w = (v.w > 0.f) ? v.w : NEG_SLOPE * v.w;
            }
            *(float4*)&Out[(size_t)m * CH + cx * 4] = v;
        }
    }
}

// ---------------------------------------------------------------------------
// Global mean pool + linear head
// ---------------------------------------------------------------------------
__global__ void k_gcnt(const int* __restrict__ batch) {
    int i = blockIdx.x * blockDim.x + threadIdx.x;
    if (i < NN) atomicAdd(&g_gcnt[batch[i]], 1.0f);
}

__global__ void k_poolscatter(const float* __restrict__ h, const int* __restrict__ batch) {
    int i = blockIdx.x * blockDim.x + threadIdx.x;
    if (i >= NN * CH) return;
    int node = i >> 7;
    int c = i & 127;
    atomicAdd(&g_pool[batch[node] * CH + c], h[i]);
}

__global__ void k_head(const float* __restrict__ hW, const float* __restrict__ hb,
                       float* __restrict__ out) {
    int g = blockIdx.x;
    int lane = threadIdx.x;
    float iv = 1.0f / fmaxf(g_gcnt[g], 1.0f);
    float a0 = 0.f, a1 = 0.f;
    for (int c = lane; c < CH; c += 32) {
        float p = g_pool[g * CH + c] * iv;
        a0 += p * hW[c * 2 + 0];
        a1 += p * hW[c * 2 + 1];
    }
    #pragma unroll
    for (int o = 16; o; o >>= 1) {
        a0 += __shfl_down_sync(0xffffffff, a0, o);
        a1 += __shfl_down_sync(0xffffffff, a1, o);
    }
    if (lane == 0) {
        out[g * 2 + 0] = a0 + hb[0];
        out[g * 2 + 1] = a1 + hb[1];
    }
}

// ---------------------------------------------------------------------------
// Host launch
// ---------------------------------------------------------------------------
static void* sym_addr(const void* sym) {
    void* p = nullptr;
    cudaGetSymbolAddress(&p, sym);
    return p;
}

extern "C" void kernel_launch(void* const* d_in, const int* in_sizes, int n_in,
                              void* d_out, int out_size) {
    const float* x    = (const float*)d_in[0];
    const int*   ei   = (const int*)d_in[1];
    const int*   srcp = ei;
    const int*   dstp = ei + EE;
    const int*   batch = (const int*)d_in[2];
    const float* Wl0 = (const float*)d_in[3];
    const float* Wr0 = (const float*)d_in[4];
    const float* b0  = (const float*)d_in[5];
    const float* Wl  = (const float*)d_in[6];
    const float* Wr  = (const float*)d_in[7];
    const float* bb  = (const float*)d_in[8];
    const float* hW  = (const float*)d_in[9];
    const float* hb  = (const float*)d_in[10];
    float* out = (float*)d_out;

    float* hA   = (float*)sym_addr(g_hA);
    float* hB   = (float*)sym_addr(g_hB);
    float* agg  = (float*)sym_addr(g_agg);
    int*   deg  = (int*)sym_addr(g_deg);
    float* pool = (float*)sym_addr(g_pool);
    float* gcnt = (float*)sym_addr(g_gcnt);

    const int TPB = 256;

    // --- CSR build (once per launch, inside the graph) ---
    k_zero_i<<<(NN + TPB - 1) / TPB, TPB>>>(deg, NN);
    k_count<<<(EE + TPB - 1) / TPB, TPB>>>(dstp);
    k_scan<<<1, 1024>>>();
    k_fill<<<(EE + TPB - 1) / TPB, TPB>>>(srcp, dstp);

    const int aggBlocks  = (NN * 32 + TPB - 1) / TPB;
    const int gemmBlocks = (NN + 63) / 64;

    // --- conv 0 (C_IN=64 -> 128), ReLU ---
    k_agg<64><<<aggBlocks, TPB>>>(x, agg);
    k_gemm<64, 1><<<gemmBlocks, TPB>>>(agg, x, Wl0, Wr0, b0, hA);

    // --- convs 1..11 ---
    float* hcur = hA;
    float* hnxt = hB;
    for (int i = 0; i < 11; i++) {
        int ci = i + 1;
        k_agg<128><<<aggBlocks, TPB>>>(hcur, agg);
        const float* wl = Wl + (size_t)i * CH * CH;
        const float* wr = Wr + (size_t)i * CH * CH;
        const float* bi = bb + (size_t)i * CH;
        if (ci == 11) {
            k_gemm<128, 0><<<gemmBlocks, TPB>>>(agg, hcur, wl, wr, bi, hnxt);
        } else if (ci == 3 || ci == 7) {
            k_gemm<128, 2><<<gemmBlocks, TPB>>>(agg, hcur, wl, wr, bi, hnxt);
        } else {
            k_gemm<128, 1><<<gemmBlocks, TPB>>>(agg, hcur, wl, wr, bi, hnxt);
        }
        float* t = hcur; hcur = hnxt; hnxt = t;
    }

    // --- global mean pool + head ---
    k_zero_f<<<(GG * CH + TPB - 1) / TPB, TPB>>>(pool, GG * CH);
    k_zero_f<<<(GG + TPB - 1) / TPB, TPB>>>(gcnt, GG);
    k_gcnt<<<(NN + TPB - 1) / TPB, TPB>>>(batch);
    k_poolscatter<<<(NN * CH + TPB - 1) / TPB, TPB>>>(hcur, batch);
    k_head<<<GG, 32>>>(hW, hb, out);
}

// round 4
// speedup vs baseline: 1.7112x; 1.7112x over previous
#include <cuda_runtime.h>
#include <cstddef>
#include <cstdint>

// Problem constants (fixed by the dataset)
#define NN   50000
#define EE   800000
#define GG   512
#define CH   128
#define CIN  64
#define NEG_SLOPE 0.01f

#define TILE_M 128
#define GEMM_BLOCKS ((NN + TILE_M - 1) / TILE_M)

// ---------------------------------------------------------------------------
// Device-global scratch (no allocation allowed in kernel_launch)
// ---------------------------------------------------------------------------
__device__ float g_hA[NN * CH];
__device__ float g_hB[NN * CH];
__device__ float g_agg[NN * CH];
__device__ float g_inv[NN];
__device__ int   g_deg[NN];
__device__ int   g_rowptr[NN + 1];
__device__ int   g_cursor[NN];
__device__ int   g_col[EE];
__device__ float g_pool[GG * CH];
__device__ float g_gcnt[GG];

// ---------------------------------------------------------------------------
// Utility kernels
// ---------------------------------------------------------------------------
__global__ void k_zero_f(float* p, int n) {
    int i = blockIdx.x * blockDim.x + threadIdx.x;
    if (i < n) p[i] = 0.0f;
}
__global__ void k_zero_i(int* p, int n) {
    int i = blockIdx.x * blockDim.x + threadIdx.x;
    if (i < n) p[i] = 0;
}
__global__ void k_count(const int* __restrict__ dst) {
    int i = blockIdx.x * blockDim.x + threadIdx.x;
    if (i < EE) atomicAdd(&g_deg[dst[i]], 1);
}

__global__ void k_scan() {
    __shared__ int sdata[1024];
    __shared__ int s_total;
    const int tid = threadIdx.x;
    if (tid == 0) s_total = 0;
    __syncthreads();
    for (int base = 0; base < NN; base += 1024) {
        int i = base + tid;
        int v = (i < NN) ? g_deg[i] : 0;
        sdata[tid] = v;
        __syncthreads();
        #pragma unroll
        for (int off = 1; off < 1024; off <<= 1) {
            int t = (tid >= off) ? sdata[tid - off] : 0;
            __syncthreads();
            sdata[tid] += t;
            __syncthreads();
        }
        int incl = sdata[tid];
        int excl = incl - v;
        int run = s_total;
        if (i < NN) {
            g_rowptr[i] = run + excl;
            g_cursor[i] = run + excl;
            g_inv[i] = 1.0f / (float)max(v, 1);
        }
        __syncthreads();
        if (tid == 1023) s_total = run + incl;
        __syncthreads();
    }
    if (tid == 0) g_rowptr[NN] = s_total;
}

__global__ void k_fill(const int* __restrict__ src, const int* __restrict__ dst) {
    int i = blockIdx.x * blockDim.x + threadIdx.x;
    if (i < EE) {
        int d = dst[i];
        int pos = atomicAdd(&g_cursor[d], 1);
        g_col[pos] = src[i];
    }
}

// ---------------------------------------------------------------------------
// Mean aggregation: one warp per destination node, gather-sum neighbor rows.
// ---------------------------------------------------------------------------
template <int C>
__global__ void k_agg(const float* __restrict__ h, float* __restrict__ agg) {
    int gw = (blockIdx.x * blockDim.x + threadIdx.x) >> 5;
    if (gw >= NN) return;
    int lane = threadIdx.x & 31;
    int b = g_rowptr[gw], e = g_rowptr[gw + 1];
    float iv = g_inv[gw];
    if constexpr (C == 128) {
        const float4* hp = (const float4*)h;
        float4 acc = make_float4(0.f, 0.f, 0.f, 0.f);
        for (int j = b; j < e; j++) {
            int s = g_col[j];
            float4 v = hp[s * 32 + lane];
            acc.x += v.x; acc.y += v.y; acc.z += v.z; acc.w += v.w;
        }
        float4 o;
        o.x = acc.x * iv; o.y = acc.y * iv; o.z = acc.z * iv; o.w = acc.w * iv;
        ((float4*)agg)[gw * 32 + lane] = o;
    } else {  // C == 64
        const float2* hp = (const float2*)h;
        float2 acc = make_float2(0.f, 0.f);
        for (int j = b; j < e; j++) {
            int s = g_col[j];
            float2 v = hp[s * 32 + lane];
            acc.x += v.x; acc.y += v.y;
        }
        float2 o; o.x = acc.x * iv; o.y = acc.y * iv;
        ((float2*)agg)[gw * 32 + lane] = o;
    }
}

// ---------------------------------------------------------------------------
// tf32 mma.sync fused SAGEConv GEMM.
//   Out[m][n] = [agg[m] | h[m]] @ [Wl;Wr] + bias[n], activation applied.
// KT = 2*KH (128 for conv0, 256 otherwise). BM=128, BN=128, BK=32.
// 256 threads = 8 warps in 4(m) x 2(n) grid; warp tile 32x64.
// mma.sync.aligned.m16n8k8.row.col.f32.tf32.tf32.f32
// ACT: 0=none, 1=relu, 2=leaky(0.01)
// ---------------------------------------------------------------------------
#define AS_STRIDE 36
#define BS_STRIDE 136

__device__ __forceinline__ uint32_t f2tf32(float x) {
    uint32_t u;
    asm("cvt.rna.tf32.f32 %0, %1;" : "=r"(u) : "f"(x));
    return u;
}

template <int KH, int ACT>
__global__ __launch_bounds__(256) void k_gemm_mma(
    const float* __restrict__ A,    // aggregated (pre-normalized), [NN][KH]
    const float* __restrict__ H,    // node features, [NN][KH]
    const float* __restrict__ Wl,   // [KH][128]
    const float* __restrict__ Wr,   // [KH][128]
    const float* __restrict__ bias, // [128]
    float* __restrict__ Out)        // [NN][128]
{
    constexpr int KT = 2 * KH;
    __shared__ float As[128 * AS_STRIDE];   // [m][k] padded
    __shared__ float Bs[32 * BS_STRIDE];    // [k][n] padded

    const int tid = threadIdx.x;
    const int wid = tid >> 5;
    const int lane = tid & 31;
    const int wm = wid & 3;          // warp m index (0..3)
    const int wn2 = wid >> 2;        // warp n index (0..1)
    const int m0 = blockIdx.x * TILE_M;

    float c[2][8][4];
    #pragma unroll
    for (int mf = 0; mf < 2; mf++)
        #pragma unroll
        for (int nf = 0; nf < 8; nf++)
            #pragma unroll
            for (int j = 0; j < 4; j++) c[mf][nf][j] = 0.0f;

    for (int kt = 0; kt < KT; kt += 32) {
        // ---- fill A tile (128 x 32), tf32-rounded, [m][k] stride 36 ----
        #pragma unroll
        for (int i = 0; i < 4; i++) {
            int f = i * 256 + tid;        // 0..1023 float4 slots
            int row = f >> 3;             // 0..127
            int kq = f & 7;               // 0..7 float4-within-row
            int kcat = kt + kq * 4;
            float4 v = make_float4(0.f, 0.f, 0.f, 0.f);
            int m = m0 + row;
            if (m < NN) {
                const float* p = (kcat < KH) ? (A + (size_t)m * KH + kcat)
                                             : (H + (size_t)m * KH + (kcat - KH));
                v = *(const float4*)p;
            }
            uint4 t;
            t.x = f2tf32(v.x); t.y = f2tf32(v.y); t.z = f2tf32(v.z); t.w = f2tf32(v.w);
            *(uint4*)&As[row * AS_STRIDE + kq * 4] = t;
        }
        // ---- fill B tile (32 x 128): rows of Wl/Wr directly (already [k][n]) ----
        #pragma unroll
        for (int i = 0; i < 4; i++) {
            int f = i * 256 + tid;
            int krow = f >> 5;            // 0..31
            int nq = f & 31;              // float4 column
            int kg = kt + krow;
            const float* p = (kg < KH) ? (Wl + (size_t)kg * 128)
                                       : (Wr + (size_t)(kg - KH) * 128);
            float4 v = *(const float4*)(p + nq * 4);
            uint4 t;
            t.x = f2tf32(v.x); t.y = f2tf32(v.y); t.z = f2tf32(v.z); t.w = f2tf32(v.w);
            *(uint4*)&Bs[krow * BS_STRIDE + nq * 4] = t;
        }
        __syncthreads();

        // ---- compute: 4 k8-steps of m16n8k8 ----
        #pragma unroll
        for (int k8 = 0; k8 < 4; k8++) {
            uint32_t afr[2][4];
            const int ar = wm * 32 + (lane >> 2);
            const int ak = k8 * 8 + (lane & 3);
            #pragma unroll
            for (int mf = 0; mf < 2; mf++) {
                int base = (ar + mf * 16) * AS_STRIDE + ak;
                afr[mf][0] = __float_as_uint(As[base]);
                afr[mf][1] = __float_as_uint(As[base + 8 * AS_STRIDE]);
                afr[mf][2] = __float_as_uint(As[base + 4]);
                afr[mf][3] = __float_as_uint(As[base + 8 * AS_STRIDE + 4]);
            }
            uint32_t bfr[8][2];
            const int bk = k8 * 8 + (lane & 3);
            const int bn = wn2 * 64 + (lane >> 2);
            #pragma unroll
            for (int nf = 0; nf < 8; nf++) {
                int base = bk * BS_STRIDE + bn + nf * 8;
                bfr[nf][0] = __float_as_uint(Bs[base]);
                bfr[nf][1] = __float_as_uint(Bs[base + 4 * BS_STRIDE]);
            }
            #pragma unroll
            for (int mf = 0; mf < 2; mf++) {
                #pragma unroll
                for (int nf = 0; nf < 8; nf++) {
                    asm volatile(
                        "mma.sync.aligned.m16n8k8.row.col.f32.tf32.tf32.f32 "
                        "{%0,%1,%2,%3}, {%4,%5,%6,%7}, {%8,%9}, {%0,%1,%2,%3};"
                        : "+f"(c[mf][nf][0]), "+f"(c[mf][nf][1]),
                          "+f"(c[mf][nf][2]), "+f"(c[mf][nf][3])
                        : "r"(afr[mf][0]), "r"(afr[mf][1]),
                          "r"(afr[mf][2]), "r"(afr[mf][3]),
                          "r"(bfr[nf][0]), "r"(bfr[nf][1]));
                }
            }
        }
        __syncthreads();
    }

    // ---- epilogue: bias + activation + store ----
    const int colbase = wn2 * 64 + (lane & 3) * 2;
    float2 bb[8];
    #pragma unroll
    for (int nf = 0; nf < 8; nf++)
        bb[nf] = *(const float2*)(bias + colbase + nf * 8);

    #pragma unroll
    for (int mf = 0; mf < 2; mf++) {
        #pragma unroll
        for (int half = 0; half < 2; half++) {
            int m = m0 + wm * 32 + mf * 16 + (lane >> 2) + half * 8;
            if (m < NN) {
                float* orow = Out + (size_t)m * CH;
                #pragma unroll
                for (int nf = 0; nf < 8; nf++) {
                    float2 v;
                    v.x = c[mf][nf][half * 2 + 0] + bb[nf].x;
                    v.y = c[mf][nf][half * 2 + 1] + bb[nf].y;
                    if (ACT == 1) {
                        v.x = fmaxf(v.x, 0.f);
                        v.y = fmaxf(v.y, 0.f);
                    } else if (ACT == 2) {
                        v.x = (v.x > 0.f) ? v.x : NEG_SLOPE * v.x;
                        v.y = (v.y > 0.f) ? v.y : NEG_SLOPE * v.y;
                    }
                    *(float2*)(orow + colbase + nf * 8) = v;
                }
            }
        }
    }
}

// ---------------------------------------------------------------------------
// Global mean pool + linear head
// ---------------------------------------------------------------------------
__global__ void k_gcnt(const int* __restrict__ batch) {
    int i = blockIdx.x * blockDim.x + threadIdx.x;
    if (i < NN) atomicAdd(&g_gcnt[batch[i]], 1.0f);
}

__global__ void k_poolscatter(const float* __restrict__ h, const int* __restrict__ batch) {
    int i = blockIdx.x * blockDim.x + threadIdx.x;
    if (i >= NN * CH) return;
    int node = i >> 7;
    int c = i & 127;
    atomicAdd(&g_pool[batch[node] * CH + c], h[i]);
}

__global__ void k_head(const float* __restrict__ hW, const float* __restrict__ hb,
                       float* __restrict__ out) {
    int g = blockIdx.x;
    int lane = threadIdx.x;
    float iv = 1.0f / fmaxf(g_gcnt[g], 1.0f);
    float a0 = 0.f, a1 = 0.f;
    for (int c = lane; c < CH; c += 32) {
        float p = g_pool[g * CH + c] * iv;
        a0 += p * hW[c * 2 + 0];
        a1 += p * hW[c * 2 + 1];
    }
    #pragma unroll
    for (int o = 16; o; o >>= 1) {
        a0 += __shfl_down_sync(0xffffffff, a0, o);
        a1 += __shfl_down_sync(0xffffffff, a1, o);
    }
    if (lane == 0) {
        out[g * 2 + 0] = a0 + hb[0];
        out[g * 2 + 1] = a1 + hb[1];
    }
}

// ---------------------------------------------------------------------------
// Host launch
// ---------------------------------------------------------------------------
static void* sym_addr(const void* sym) {
    void* p = nullptr;
    cudaGetSymbolAddress(&p, sym);
    return p;
}

extern "C" void kernel_launch(void* const* d_in, const int* in_sizes, int n_in,
                              void* d_out, int out_size) {
    const float* x    = (const float*)d_in[0];
    const int*   ei   = (const int*)d_in[1];
    const int*   srcp = ei;
    const int*   dstp = ei + EE;
    const int*   batch = (const int*)d_in[2];
    const float* Wl0 = (const float*)d_in[3];
    const float* Wr0 = (const float*)d_in[4];
    const float* b0  = (const float*)d_in[5];
    const float* Wl  = (const float*)d_in[6];
    const float* Wr  = (const float*)d_in[7];
    const float* bb  = (const float*)d_in[8];
    const float* hW  = (const float*)d_in[9];
    const float* hb  = (const float*)d_in[10];
    float* out = (float*)d_out;

    float* hA   = (float*)sym_addr(g_hA);
    float* hB   = (float*)sym_addr(g_hB);
    float* agg  = (float*)sym_addr(g_agg);
    int*   deg  = (int*)sym_addr(g_deg);
    float* pool = (float*)sym_addr(g_pool);
    float* gcnt = (float*)sym_addr(g_gcnt);

    const int TPB = 256;

    // --- CSR build (once per launch, inside the graph) ---
    k_zero_i<<<(NN + TPB - 1) / TPB, TPB>>>(deg, NN);
    k_count<<<(EE + TPB - 1) / TPB, TPB>>>(dstp);
    k_scan<<<1, 1024>>>();
    k_fill<<<(EE + TPB - 1) / TPB, TPB>>>(srcp, dstp);

    const int aggBlocks = (NN * 32 + TPB - 1) / TPB;

    // --- conv 0 (C_IN=64 -> 128), ReLU ---
    k_agg<64><<<aggBlocks, TPB>>>(x, agg);
    k_gemm_mma<64, 1><<<GEMM_BLOCKS, TPB>>>(agg, x, Wl0, Wr0, b0, hA);

    // --- convs 1..11 ---
    float* hcur = hA;
    float* hnxt = hB;
    for (int i = 0; i < 11; i++) {
        int ci = i + 1;
        k_agg<128><<<aggBlocks, TPB>>>(hcur, agg);
        const float* wl = Wl + (size_t)i * CH * CH;
        const float* wr = Wr + (size_t)i * CH * CH;
        const float* bi = bb + (size_t)i * CH;
        if (ci == 11) {
            k_gemm_mma<128, 0><<<GEMM_BLOCKS, TPB>>>(agg, hcur, wl, wr, bi, hnxt);
        } else if (ci == 3 || ci == 7) {
            k_gemm_mma<128, 2><<<GEMM_BLOCKS, TPB>>>(agg, hcur, wl, wr, bi, hnxt);
        } else {
            k_gemm_mma<128, 1><<<GEMM_BLOCKS, TPB>>>(agg, hcur, wl, wr, bi, hnxt);
        }
        float* t = hcur; hcur = hnxt; hnxt = t;
    }

    // --- global mean pool + head ---
    k_zero_f<<<(GG * CH + TPB - 1) / TPB, TPB>>>(pool, GG * CH);
    k_zero_f<<<(GG + TPB - 1) / TPB, TPB>>>(gcnt, GG);
    k_gcnt<<<(NN + TPB - 1) / TPB, TPB>>>(batch);
    k_poolscatter<<<(NN * CH + TPB - 1) / TPB, TPB>>>(hcur, batch);
    k_head<<<GG, 32>>>(hW, hb, out);
}

// round 6
// speedup vs baseline: 2.2353x; 1.3063x over previous
#include <cuda_runtime.h>
#include <cuda_fp16.h>
#include <cstddef>
#include <cstdint>

// Problem constants (fixed by the dataset)
#define NN   50000
#define EE   800000
#define GG   512
#define CH   128
#define CIN  64
#define NEG_SLOPE 0.01f

#define TILE_M 128
#define GEMM_BLOCKS ((NN + TILE_M - 1) / TILE_M)

// ---------------------------------------------------------------------------
// Device-global scratch (no allocation allowed in kernel_launch)
// ---------------------------------------------------------------------------
__device__ __half g_h16A[NN * CH];
__device__ __half g_h16B[NN * CH];
__device__ __half g_agg16[NN * CH];
__device__ __half g_x16[NN * CIN];
__device__ __half g_W16[12 * 128 * 256];   // [layer][n=128][k=256]
__device__ float g_inv[NN];
__device__ int   g_deg[NN];
__device__ int   g_rowptr[NN + 1];
__device__ int   g_cursor[NN];
__device__ int   g_col[EE];
__device__ float g_pool[GG * CH];
__device__ float g_gcnt[GG];

// ---------------------------------------------------------------------------
// Utility kernels
// ---------------------------------------------------------------------------
__global__ void k_zero_f(float* p, int n) {
    int i = blockIdx.x * blockDim.x + threadIdx.x;
    if (i < n) p[i] = 0.0f;
}
__global__ void k_zero_i(int* p, int n) {
    int i = blockIdx.x * blockDim.x + threadIdx.x;
    if (i < n) p[i] = 0;
}
__global__ void k_count(const int* __restrict__ dst) {
    int i = blockIdx.x * blockDim.x + threadIdx.x;
    if (i < EE) atomicAdd(&g_deg[dst[i]], 1);
}

__global__ void k_scan() {
    __shared__ int sdata[1024];
    __shared__ int s_total;
    const int tid = threadIdx.x;
    if (tid == 0) s_total = 0;
    __syncthreads();
    for (int base = 0; base < NN; base += 1024) {
        int i = base + tid;
        int v = (i < NN) ? g_deg[i] : 0;
        sdata[tid] = v;
        __syncthreads();
        #pragma unroll
        for (int off = 1; off < 1024; off <<= 1) {
            int t = (tid >= off) ? sdata[tid - off] : 0;
            __syncthreads();
            sdata[tid] += t;
            __syncthreads();
        }
        int incl = sdata[tid];
        int excl = incl - v;
        int run = s_total;
        if (i < NN) {
            g_rowptr[i] = run + excl;
            g_cursor[i] = run + excl;
            g_inv[i] = 1.0f / (float)max(v, 1);
        }
        __syncthreads();
        if (tid == 1023) s_total = run + incl;
        __syncthreads();
    }
    if (tid == 0) g_rowptr[NN] = s_total;
}

__global__ void k_fill(const int* __restrict__ src, const int* __restrict__ dst) {
    int i = blockIdx.x * blockDim.x + threadIdx.x;
    if (i < EE) {
        int d = dst[i];
        int pos = atomicAdd(&g_cursor[d], 1);
        g_col[pos] = src[i];
    }
}

// Convert input features x (fp32) -> fp16
__global__ void k_cvt_x(const float* __restrict__ x) {
    int i = blockIdx.x * blockDim.x + threadIdx.x;
    if (i < NN * CIN) g_x16[i] = __float2half_rn(x[i]);
}

// Build transposed fp16 weight table: g_W16[l][n][k] = Wcat_l[k][n]
__global__ void k_w16(const float* __restrict__ Wl0, const float* __restrict__ Wr0,
                      const float* __restrict__ Wl, const float* __restrict__ Wr) {
    int idx = blockIdx.x * blockDim.x + threadIdx.x;
    if (idx >= 12 * 128 * 256) return;
    int l = idx >> 15;
    int n = (idx >> 8) & 127;
    int k = idx & 255;
    float v = 0.0f;
    if (l == 0) {
        if (k < 64)       v = Wl0[k * 128 + n];
        else if (k < 128) v = Wr0[(k - 64) * 128 + n];
    } else {
        int i = l - 1;
        if (k < 128) v = Wl[(size_t)i * 128 * 128 + k * 128 + n];
        else         v = Wr[(size_t)i * 128 * 128 + (k - 128) * 128 + n];
    }
    g_W16[idx] = __float2half_rn(v);
}

// ---------------------------------------------------------------------------
// Mean aggregation (fp16 in/out, fp32 accumulate): one warp per node.
// ---------------------------------------------------------------------------
template <int C>
__global__ void k_agg16(const __half* __restrict__ h, __half* __restrict__ agg) {
    int gw = (blockIdx.x * blockDim.x + threadIdx.x) >> 5;
    if (gw >= NN) return;
    int lane = threadIdx.x & 31;
    int b = g_rowptr[gw], e = g_rowptr[gw + 1];
    float iv = g_inv[gw];
    if constexpr (C == 128) {
        // lane handles 4 channels: uint2 = 4 halves
        const uint2* hp = (const uint2*)h;          // 4 halves per elem, 32 per row
        float4 acc = make_float4(0.f, 0.f, 0.f, 0.f);
        for (int j = b; j < e; j++) {
            int s = g_col[j];
            uint2 u = hp[s * 32 + lane];
            float2 a = __half22float2(*(const __half2*)&u.x);
            float2 c2 = __half22float2(*(const __half2*)&u.y);
            acc.x += a.x; acc.y += a.y; acc.z += c2.x; acc.w += c2.y;
        }
        uint2 o;
        *(__half2*)&o.x = __floats2half2_rn(acc.x * iv, acc.y * iv);
        *(__half2*)&o.y = __floats2half2_rn(acc.z * iv, acc.w * iv);
        ((uint2*)agg)[gw * 32 + lane] = o;
    } else {  // C == 64: lane handles 2 channels
        const uint32_t* hp = (const uint32_t*)h;    // 2 halves per elem, 32 per row
        float2 acc = make_float2(0.f, 0.f);
        for (int j = b; j < e; j++) {
            int s = g_col[j];
            uint32_t u = hp[s * 32 + lane];
            float2 a = __half22float2(*(const __half2*)&u);
            acc.x += a.x; acc.y += a.y;
        }
        uint32_t o;
        *(__half2*)&o = __floats2half2_rn(acc.x * iv, acc.y * iv);
        ((uint32_t*)agg)[gw * 32 + lane] = o;
    }
}

// ---------------------------------------------------------------------------
// fp16 mma.sync fused SAGEConv GEMM.
//   Out[m][n] = [agg16[m] | h16[m]] @ W16_l^T + bias[n], activation applied.
// KT = 2*KH (128 conv0, 256 others). BM=128, BN=128, BK=32.
// 256 threads = 8 warps, 4(m) x 2(n); warp tile 32x64.
// mma.sync.aligned.m16n8k16.row.col.f32.f16.f16.f32, fp32 accum.
// ACT: 0=none, 1=relu, 2=leaky(0.01)
// ---------------------------------------------------------------------------
#define AS_STR 40   // halves per row (32 + 8 pad) -> conflict-free fragment LDS
#define BS_STR 40

template <int KH, int ACT>
__global__ __launch_bounds__(256) void k_gemm16(
    const __half* __restrict__ A,    // aggregated fp16, [NN][KH]
    const __half* __restrict__ H,    // node features fp16, [NN][KH]
    const __half* __restrict__ W16,  // [128][256] transposed fp16 weights for layer
    const float* __restrict__ bias,  // [128]
    __half* __restrict__ Out)        // [NN][128]
{
    constexpr int KT = 2 * KH;
    __shared__ __half As[128 * AS_STR];   // [m][k]
    __shared__ __half Bs[128 * BS_STR];   // [n][k]

    const int tid = threadIdx.x;
    const int wid = tid >> 5;
    const int lane = tid & 31;
    const int wm = wid & 3;
    const int wn2 = wid >> 2;
    const int m0 = blockIdx.x * TILE_M;

    // fill indices: thread t -> row t>>1, 16-half chunk (t&1)
    const int frow = tid >> 1;
    const int foff = (tid & 1) * 16;

    float c[2][8][4];
    #pragma unroll
    for (int mf = 0; mf < 2; mf++)
        #pragma unroll
        for (int nf = 0; nf < 8; nf++)
            #pragma unroll
            for (int j = 0; j < 4; j++) c[mf][nf][j] = 0.0f;

    for (int kt = 0; kt < KT; kt += 32) {
        // ---- A tile (128 x 32 halves): 16-half contiguous chunk per thread ----
        {
            int kcat = kt + foff;
            int m = m0 + frow;
            uint4 v0 = make_uint4(0, 0, 0, 0), v1 = make_uint4(0, 0, 0, 0);
            if (m < NN) {
                const __half* p = (kcat < KH) ? (A + (size_t)m * KH + kcat)
                                              : (H + (size_t)m * KH + (kcat - KH));
                v0 = *(const uint4*)p;
                v1 = *(const uint4*)(p + 8);
            }
            *(uint4*)&As[frow * AS_STR + foff] = v0;
            *(uint4*)&As[frow * AS_STR + foff + 8] = v1;
        }
        // ---- B tile (128 n-rows x 32 halves) from pre-transposed W16 ----
        {
            const __half* p = W16 + (size_t)frow * 256 + kt + foff;
            *(uint4*)&Bs[frow * BS_STR + foff] = *(const uint4*)p;
            *(uint4*)&Bs[frow * BS_STR + foff + 8] = *(const uint4*)(p + 8);
        }
        __syncthreads();

        // ---- compute: 2 k16-steps ----
        #pragma unroll
        for (int s = 0; s < 2; s++) {
            const int ak = s * 16 + 2 * (lane & 3);
            const int arow = wm * 32 + (lane >> 2);
            uint32_t a[2][4];
            #pragma unroll
            for (int mf = 0; mf < 2; mf++) {
                int r = arow + mf * 16;
                a[mf][0] = *(const uint32_t*)&As[r * AS_STR + ak];
                a[mf][1] = *(const uint32_t*)&As[(r + 8) * AS_STR + ak];
                a[mf][2] = *(const uint32_t*)&As[r * AS_STR + ak + 8];
                a[mf][3] = *(const uint32_t*)&As[(r + 8) * AS_STR + ak + 8];
            }
            const int bn0 = wn2 * 64 + (lane >> 2);
            uint32_t bfr[8][2];
            #pragma unroll
            for (int nf = 0; nf < 8; nf++) {
                int n = bn0 + nf * 8;
                bfr[nf][0] = *(const uint32_t*)&Bs[n * BS_STR + ak];
                bfr[nf][1] = *(const uint32_t*)&Bs[n * BS_STR + ak + 8];
            }
            #pragma unroll
            for (int mf = 0; mf < 2; mf++) {
                #pragma unroll
                for (int nf = 0; nf < 8; nf++) {
                    asm volatile(
                        "mma.sync.aligned.m16n8k16.row.col.f32.f16.f16.f32 "
                        "{%0,%1,%2,%3}, {%4,%5,%6,%7}, {%8,%9}, {%0,%1,%2,%3};"
                        : "+f"(c[mf][nf][0]), "+f"(c[mf][nf][1]),
                          "+f"(c[mf][nf][2]), "+f"(c[mf][nf][3])
                        : "r"(a[mf][0]), "r"(a[mf][1]), "r"(a[mf][2]), "r"(a[mf][3]),
                          "r"(bfr[nf][0]), "r"(bfr[nf][1]));
                }
            }
        }
        __syncthreads();
    }

    // ---- epilogue: bias + activation + fp16 store ----
    const int colbase = wn2 * 64 + (lane & 3) * 2;
    float2 bb[8];
    #pragma unroll
    for (int nf = 0; nf < 8; nf++)
        bb[nf] = *(const float2*)(bias + colbase + nf * 8);

    #pragma unroll
    for (int mf = 0; mf < 2; mf++) {
        #pragma unroll
        for (int half = 0; half < 2; half++) {
            int m = m0 + wm * 32 + mf * 16 + (lane >> 2) + half * 8;
            if (m < NN) {
                __half* orow = Out + (size_t)m * CH;
                #pragma unroll
                for (int nf = 0; nf < 8; nf++) {
                    float vx = c[mf][nf][half * 2 + 0] + bb[nf].x;
                    float vy = c[mf][nf][half * 2 + 1] + bb[nf].y;
                    if (ACT == 1) {
                        vx = fmaxf(vx, 0.f);
                        vy = fmaxf(vy, 0.f);
                    } else if (ACT == 2) {
                        vx = (vx > 0.f) ? vx : NEG_SLOPE * vx;
                        vy = (vy > 0.f) ? vy : NEG_SLOPE * vy;
                    }
                    *(__half2*)(orow + colbase + nf * 8) = __floats2half2_rn(vx, vy);
                }
            }
        }
    }
}

// ---------------------------------------------------------------------------
// Global mean pool + linear head
// ---------------------------------------------------------------------------
__global__ void k_gcnt(const int* __restrict__ batch) {
    int i = blockIdx.x * blockDim.x + threadIdx.x;
    if (i < NN) atomicAdd(&g_gcnt[batch[i]], 1.0f);
}

__global__ void k_poolscatter16(const __half* __restrict__ h, const int* __restrict__ batch) {
    int i = blockIdx.x * blockDim.x + threadIdx.x;
    if (i >= NN * CH) return;
    int node = i >> 7;
    int c = i & 127;
    atomicAdd(&g_pool[batch[node] * CH + c], __half2float(h[i]));
}

__global__ void k_head(const float* __restrict__ hW, const float* __restrict__ hb,
                       float* __restrict__ out) {
    int g = blockIdx.x;
    int lane = threadIdx.x;
    float iv = 1.0f / fmaxf(g_gcnt[g], 1.0f);
    float a0 = 0.f, a1 = 0.f;
    for (int c = lane; c < CH; c += 32) {
        float p = g_pool[g * CH + c] * iv;
        a0 += p * hW[c * 2 + 0];
        a1 += p * hW[c * 2 + 1];
    }
    #pragma unroll
    for (int o = 16; o; o >>= 1) {
        a0 += __shfl_down_sync(0xffffffff, a0, o);
        a1 += __shfl_down_sync(0xffffffff, a1, o);
    }
    if (lane == 0) {
        out[g * 2 + 0] = a0 + hb[0];
        out[g * 2 + 1] = a1 + hb[1];
    }
}

// ---------------------------------------------------------------------------
// Host launch
// ---------------------------------------------------------------------------
static void* sym_addr(const void* sym) {
    void* p = nullptr;
    cudaGetSymbolAddress(&p, sym);
    return p;
}

extern "C" void kernel_launch(void* const* d_in, const int* in_sizes, int n_in,
                              void* d_out, int out_size) {
    const float* x    = (const float*)d_in[0];
    const int*   ei   = (const int*)d_in[1];
    const int*   srcp = ei;
    const int*   dstp = ei + EE;
    const int*   batch = (const int*)d_in[2];
    const float* Wl0 = (const float*)d_in[3];
    const float* Wr0 = (const float*)d_in[4];
    const float* b0  = (const float*)d_in[5];
    const float* Wl  = (const float*)d_in[6];
    const float* Wr  = (const float*)d_in[7];
    const float* bb  = (const float*)d_in[8];
    const float* hW  = (const float*)d_in[9];
    const float* hb  = (const float*)d_in[10];
    float* out = (float*)d_out;

    __half* h16A  = (__half*)sym_addr(g_h16A);
    __half* h16B  = (__half*)sym_addr(g_h16B);
    __half* agg16 = (__half*)sym_addr(g_agg16);
    __half* x16   = (__half*)sym_addr(g_x16);
    __half* W16   = (__half*)sym_addr(g_W16);
    int*    deg   = (int*)sym_addr(g_deg);
    float*  pool  = (float*)sym_addr(g_pool);
    float*  gcnt  = (float*)sym_addr(g_gcnt);

    const int TPB = 256;

    // --- CSR build + fp16 conversions (inside the graph, once per launch) ---
    k_zero_i<<<(NN + TPB - 1) / TPB, TPB>>>(deg, NN);
    k_count<<<(EE + TPB - 1) / TPB, TPB>>>(dstp);
    k_cvt_x<<<(NN * CIN + TPB - 1) / TPB, TPB>>>(x);
    k_w16<<<(12 * 128 * 256 + TPB - 1) / TPB, TPB>>>(Wl0, Wr0, Wl, Wr);
    k_scan<<<1, 1024>>>();
    k_fill<<<(EE + TPB - 1) / TPB, TPB>>>(srcp, dstp);

    const int aggBlocks = (NN * 32 + TPB - 1) / TPB;

    // --- conv 0 (C_IN=64 -> 128), ReLU ---
    k_agg16<64><<<aggBlocks, TPB>>>(x16, agg16);
    k_gemm16<64, 1><<<GEMM_BLOCKS, TPB>>>(agg16, x16, W16, b0, h16A);

    // --- convs 1..11 ---
    __half* hcur = h16A;
    __half* hnxt = h16B;
    for (int i = 0; i < 11; i++) {
        int ci = i + 1;
        k_agg16<128><<<aggBlocks, TPB>>>(hcur, agg16);
        const __half* wt = W16 + (size_t)(i + 1) * 128 * 256;
        const float* bi = bb + (size_t)i * CH;
        if (ci == 11) {
            k_gemm16<128, 0><<<GEMM_BLOCKS, TPB>>>(agg16, hcur, wt, bi, hnxt);
        } else if (ci == 3 || ci == 7) {
            k_gemm16<128, 2><<<GEMM_BLOCKS, TPB>>>(agg16, hcur, wt, bi, hnxt);
        } else {
            k_gemm16<128, 1><<<GEMM_BLOCKS, TPB>>>(agg16, hcur, wt, bi, hnxt);
        }
        __half* t = hcur; hcur = hnxt; hnxt = t;
    }

    // --- global mean pool + head ---
    k_zero_f<<<(GG * CH + TPB - 1) / TPB, TPB>>>(pool, GG * CH);
    k_zero_f<<<(GG + TPB - 1) / TPB, TPB>>>(gcnt, GG);
    k_gcnt<<<(NN + TPB - 1) / TPB, TPB>>>(batch);
    k_poolscatter16<<<(NN * CH + TPB - 1) / TPB, TPB>>>(hcur, batch);
    k_head<<<GG, 32>>>(hW, hb, out);
}